// round 6
// baseline (speedup 1.0000x reference)
#include <cuda_runtime.h>
#include <math.h>

// ---------------------------------------------------------------------------
// CapsNet forward, B=32. Dominant cost: FC 102400->9216 (3.77 GB weights).
// Split-K GEMM using packed fp32 fma.rn.f32x2, register-resident weights
// (each weight read from DRAM exactly once), broadcast-only smem activations.
// ---------------------------------------------------------------------------

#define FC_M      9216
#define FC_K      102400
#define FC_SPLITK 16
#define FC_KSEG   6400      // FC_K / FC_SPLITK
#define FC_NCH    400       // FC_KSEG / 16

// output section offsets (concatenated tuple, fp32)
#define OFF_LOGITS 0
#define OFF_RECON  320
#define OFF_PRIM   25408
#define OFF_DIGIT  320320
#define OFF_C      325440
#define OFF_B      694080

// ---------------- device scratch (static; allocations are forbidden) -------
__device__ __align__(16) float g_xT[784 * 32];
__device__ __align__(16) float g_flatT[FC_K * 32];                 // 13.1 MB
__device__ __align__(16) float g_Cpart[FC_SPLITK * FC_M * 32];     // 18.9 MB
__device__ __align__(16) float g_capsT[FC_M * 32];
__device__ __align__(16) float g_uhatT[10 * 1152 * 16 * 32];       // 23.6 MB
__device__ __align__(16) float g_bT[10 * 1152 * 32];
__device__ __align__(16) float g_cT[10 * 1152 * 32];
__device__ __align__(16) float g_spart[10 * 36 * 16 * 32];
__device__ __align__(16) float g_v[10 * 32 * 16];
__device__ __align__(16) float g_masked[160 * 32];
__device__ __align__(16) float g_d1[512 * 32];
__device__ __align__(16) float g_d2[1024 * 32];

// ---------------- packed fp32 helpers (sm_100+) ----------------------------
__device__ __forceinline__ void fma2(unsigned long long& d,
                                     unsigned long long a,
                                     unsigned long long b) {
    asm("fma.rn.f32x2 %0, %1, %2, %0;" : "+l"(d) : "l"(a), "l"(b));
}
__device__ __forceinline__ unsigned long long dup2(float w) {
    unsigned long long r;
    asm("mov.b64 %0, {%1, %1};" : "=l"(r) : "f"(w));
    return r;
}
__device__ __forceinline__ float f4e(const float4& v, int e) {
    return e == 0 ? v.x : e == 1 ? v.y : e == 2 ? v.z : v.w;
}

// ---------------------------------------------------------------------------
// 0) x [32][784] -> xT [784][32]
// ---------------------------------------------------------------------------
__global__ void xT_kernel(const float* __restrict__ x) {
    int idx = blockIdx.x * 256 + threadIdx.x;
    if (idx < 784 * 32) {
        int b = idx / 784;
        int pix = idx - b * 784;
        g_xT[pix * 32 + b] = x[idx];
    }
}

// ---------------------------------------------------------------------------
// 1) conv 9x9 VALID + bias + relu -> flatT[k][b], k = oc*400 + oh*20 + ow
//    102400 k values * 32 batches  ->  grid 12800 x 256
// ---------------------------------------------------------------------------
__global__ void conv_kernel(const float* __restrict__ cw,
                            const float* __restrict__ cb) {
    int idx = blockIdx.x * 256 + threadIdx.x;   // 3,276,800 threads
    int b = idx & 31;
    int k = idx >> 5;                            // 0 .. 102399
    int oc = k / 400;
    int pos = k - oc * 400;
    int oh = pos / 20;
    int ow = pos - oh * 20;
    float acc = cb[oc];
    const float* wp = cw + oc * 81;
#pragma unroll
    for (int r = 0; r < 9; ++r) {
#pragma unroll
        for (int cc = 0; cc < 9; ++cc) {
            acc = fmaf(g_xT[((oh + r) * 28 + ow + cc) * 32 + b], wp[r * 9 + cc], acc);
        }
    }
    g_flatT[(size_t)k * 32 + b] = fmaxf(acc, 0.f);
}

// ---------------------------------------------------------------------------
// 2) FC GEMM: Cpart[sk][m][b] = sum_{k in seg} fc_w[m][k] * flatT[k][b]
//    128 threads, thread owns 2 rows (t, t+128) x 32 b. Weights prefetched
//    one float4-group ahead in registers; activations double-buffered in a
//    4 KB smem tile read only as warp-uniform broadcasts.
// ---------------------------------------------------------------------------
__global__ void __launch_bounds__(128)
fc_gemm_kernel(const float* __restrict__ fcw) {
    __shared__ __align__(16) float4 fsh[2][128];  // [16 k][32 b]

    const int t = threadIdx.x;
    const int mbase = blockIdx.x * 256;
    const long long kbase = (long long)blockIdx.y * FC_KSEG;
    const float4* fsrc = (const float4*)(g_flatT + kbase * 32);

    const float* wp0 = fcw + (size_t)(mbase + t) * FC_K + kbase;
    const float* wp1 = wp0 + (size_t)128 * FC_K;

    unsigned long long acc0[16], acc1[16];
#pragma unroll
    for (int i = 0; i < 16; ++i) { acc0[i] = 0ull; acc1[i] = 0ull; }

    fsh[0][t] = fsrc[t];
    __syncthreads();

    // weight pipeline: w0/w1 hold the group about to be consumed
    float4 w0 = *(const float4*)(wp0);
    float4 w1 = *(const float4*)(wp1);

    for (int c = 0; c < FC_NCH; ++c) {
        const int buf = c & 1;
        const bool more = (c + 1) < FC_NCH;
        float4 fnext;
        if (more) fnext = fsrc[(c + 1) * 128 + t];

#pragma unroll
        for (int g = 0; g < 4; ++g) {
            const float4 cw0 = w0, cw1 = w1;
            // prefetch next weight group (next g, or g=0 of next chunk)
            int nc = c, ng = g + 1;
            if (ng == 4) { ng = 0; nc = c + 1; }
            if (nc < FC_NCH) {
                w0 = *(const float4*)(wp0 + nc * 16 + ng * 4);
                w1 = *(const float4*)(wp1 + nc * 16 + ng * 4);
            }
#pragma unroll
            for (int e = 0; e < 4; ++e) {
                const int k = g * 4 + e;
                const unsigned long long wd0 = dup2(f4e(cw0, e));
                const unsigned long long wd1 = dup2(f4e(cw1, e));
#pragma unroll
                for (int q = 0; q < 8; ++q) {
                    const ulonglong2 ff =
                        *(const ulonglong2*)&fsh[buf][k * 8 + q];  // broadcast
                    fma2(acc0[2 * q],     wd0, ff.x);
                    fma2(acc0[2 * q + 1], wd0, ff.y);
                    fma2(acc1[2 * q],     wd1, ff.x);
                    fma2(acc1[2 * q + 1], wd1, ff.y);
                }
            }
        }
        if (more) fsh[buf ^ 1][t] = fnext;
        __syncthreads();
    }

    float* dst0 = g_Cpart + ((size_t)blockIdx.y * FC_M + mbase + t) * 32;
    float* dst1 = dst0 + (size_t)128 * 32;
#pragma unroll
    for (int q = 0; q < 8; ++q) {
        float2 a = *(float2*)&acc0[2 * q];
        float2 b = *(float2*)&acc0[2 * q + 1];
        *(float4*)(dst0 + q * 4) = make_float4(a.x, a.y, b.x, b.y);
        a = *(float2*)&acc1[2 * q];
        b = *(float2*)&acc1[2 * q + 1];
        *(float4*)(dst1 + q * 4) = make_float4(a.x, a.y, b.x, b.y);
    }
}

// ---------------------------------------------------------------------------
// 3) reduce split-K + bias + squash -> primary caps output + capsT scratch
// ---------------------------------------------------------------------------
__global__ void caps_kernel(const float* __restrict__ fcb,
                            float* __restrict__ out) {
    int idx = blockIdx.x * 256 + threadIdx.x;   // 36864
    int b = idx & 31;
    int cap = idx >> 5;
    float pc[8];
    float n2 = 0.f;
#pragma unroll
    for (int d = 0; d < 8; ++d) {
        int m = cap * 8 + d;
        float v = fcb[m];
#pragma unroll
        for (int s = 0; s < FC_SPLITK; ++s)
            v += g_Cpart[((size_t)s * FC_M + m) * 32 + b];
        pc[d] = v;
        n2 += v * v;
    }
    float scale = n2 / (1.f + n2);
    float inv = 1.f / sqrtf(n2);
#pragma unroll
    for (int d = 0; d < 8; ++d) {
        float o = scale * (pc[d] * inv + 1e-8f);
        out[OFF_PRIM + (size_t)b * 9216 + cap * 8 + d] = o;
        g_capsT[(cap * 8 + d) * 32 + b] = o;
    }
}

// ---------------------------------------------------------------------------
// 4) u_hat[b,n,p,d] = sum_i W[0,n,p,d,i] * caps[b,p,i] -> g_uhatT[n][p][d][b]
// ---------------------------------------------------------------------------
__global__ void uhat_kernel(const float* __restrict__ W) {
    int idx = blockIdx.x * 256 + threadIdx.x;   // 368640
    int b = idx & 31;
    int r = idx >> 5;                            // n*1152 + p
    int p = r % 1152;
    float caps[8];
#pragma unroll
    for (int i = 0; i < 8; ++i) caps[i] = g_capsT[(p * 8 + i) * 32 + b];
    const float* Wp = W + (size_t)r * 128;       // warp-uniform broadcast
    float* up = g_uhatT + (size_t)r * 512 + b;
#pragma unroll
    for (int d = 0; d < 16; ++d) {
        float a = 0.f;
#pragma unroll
        for (int i = 0; i < 8; ++i) a = fmaf(Wp[d * 8 + i], caps[i], a);
        up[d * 32] = a;
    }
}

// ---------------------------------------------------------------------------
// 5a) partial s sums over p-chunks of 32: spart[n][ch][d][b]
// ---------------------------------------------------------------------------
__global__ void rout_sv_kernel(int uniformC) {
    int n = blockIdx.x / 36;
    int ch = blockIdx.x - n * 36;
    int t = threadIdx.x;                         // 512 = 16 d * 32 b
    int b = t & 31;
    int d = t >> 5;
    int rbase = n * 1152 + ch * 32;
    float a = 0.f;
#pragma unroll 8
    for (int pp = 0; pp < 32; ++pp) {
        size_t r = rbase + pp;
        float c = uniformC ? 0.1f : g_cT[r * 32 + b];
        a = fmaf(c, g_uhatT[(r * 16 + d) * 32 + b], a);
    }
    g_spart[(((size_t)n * 36 + ch) * 16 + d) * 32 + b] = a;
}

// 5b) reduce partials + squash -> v (and digit caps output when final)
__global__ void rout_squash_kernel(int final_, float* __restrict__ out) {
    int t = threadIdx.x;                         // 320
    int b = t & 31;
    int n = t >> 5;
    float s[16];
    float n2 = 0.f;
#pragma unroll
    for (int d = 0; d < 16; ++d) {
        float a = 0.f;
        for (int ch = 0; ch < 36; ++ch)
            a += g_spart[(((size_t)n * 36 + ch) * 16 + d) * 32 + b];
        s[d] = a;
        n2 += a * a;
    }
    float scale = n2 / (1.f + n2);
    float inv = 1.f / sqrtf(n2);
#pragma unroll
    for (int d = 0; d < 16; ++d) {
        float v = scale * (s[d] * inv + 1e-8f);
        g_v[(n * 32 + b) * 16 + d] = v;
        if (final_) out[OFF_DIGIT + (size_t)b * 160 + n * 16 + d] = v;
    }
}

// 5c) b += sum_d u_hat * v   (first iteration: b = uv, since b starts at 0)
__global__ void rout_update_kernel(int first) {
    int idx = blockIdx.x * 256 + threadIdx.x;   // 368640
    int b = idx & 31;
    int r = idx >> 5;
    int n = r / 1152;
    const float* up = g_uhatT + (size_t)r * 512 + b;
    const float* vp = g_v + ((size_t)n * 32 + b) * 16;
    float a = 0.f;
#pragma unroll
    for (int d = 0; d < 16; ++d) a = fmaf(up[d * 32], vp[d], a);
    size_t o = (size_t)r * 32 + b;
    g_bT[o] = (first ? 0.f : g_bT[o]) + a;
}

// 5d) c = softmax over n of b; optionally emit final c and b to output
__global__ void softmax_kernel(int write_out, float* __restrict__ out) {
    int idx = blockIdx.x * 256 + threadIdx.x;   // 36864
    int b = idx & 31;
    int p = idx >> 5;
    float bv[10];
    float m = -1e30f;
#pragma unroll
    for (int n = 0; n < 10; ++n) {
        bv[n] = g_bT[((size_t)n * 1152 + p) * 32 + b];
        m = fmaxf(m, bv[n]);
    }
    float e[10];
    float sum = 0.f;
#pragma unroll
    for (int n = 0; n < 10; ++n) {
        e[n] = expf(bv[n] - m);
        sum += e[n];
    }
    float invs = 1.f / sum;
#pragma unroll
    for (int n = 0; n < 10; ++n) {
        float c = e[n] * invs;
        g_cT[((size_t)n * 1152 + p) * 32 + b] = c;
        if (write_out) {
            out[OFF_C + ((size_t)b * 10 + n) * 1152 + p] = c;
            out[OFF_B + ((size_t)b * 10 + n) * 1152 + p] = bv[n];
        }
    }
}

// ---------------------------------------------------------------------------
// 6) logits = ||digit||, argmax (first max), masked -> g_masked[i][b]
// ---------------------------------------------------------------------------
__global__ void logits_kernel(float* __restrict__ out) {
    int b = threadIdx.x;                         // 32
    float dg[160];
    for (int i = 0; i < 160; ++i) dg[i] = out[OFF_DIGIT + (size_t)b * 160 + i];
    float best = -1.f;
    int am = 0;
    for (int n = 0; n < 10; ++n) {
        float n2 = 0.f;
        for (int d = 0; d < 16; ++d) {
            float v = dg[n * 16 + d];
            n2 += v * v;
        }
        float lg = sqrtf(n2);
        out[OFF_LOGITS + b * 10 + n] = lg;
        if (lg > best) { best = lg; am = n; }
    }
    for (int n = 0; n < 10; ++n)
        for (int d = 0; d < 16; ++d)
            g_masked[(n * 16 + d) * 32 + b] = (n == am) ? dg[n * 16 + d] : 0.f;
}

// ---------------------------------------------------------------------------
// 7) decoder MLP (warp lane = batch; 8 units per block row)
// ---------------------------------------------------------------------------
__global__ void dec1_kernel(const float* __restrict__ Wt,
                            const float* __restrict__ bias) {
    int idx = blockIdx.x * 256 + threadIdx.x;   // 512*32
    int b = idx & 31, o = idx >> 5;
    const float* w = Wt + (size_t)o * 160;
    float a0 = 0.f, a1 = 0.f, a2 = 0.f, a3 = 0.f;
#pragma unroll 4
    for (int i = 0; i < 160; i += 4) {
        a0 = fmaf(w[i],     g_masked[(i)     * 32 + b], a0);
        a1 = fmaf(w[i + 1], g_masked[(i + 1) * 32 + b], a1);
        a2 = fmaf(w[i + 2], g_masked[(i + 2) * 32 + b], a2);
        a3 = fmaf(w[i + 3], g_masked[(i + 3) * 32 + b], a3);
    }
    g_d1[o * 32 + b] = fmaxf(bias[o] + ((a0 + a1) + (a2 + a3)), 0.f);
}

__global__ void dec2_kernel(const float* __restrict__ Wt,
                            const float* __restrict__ bias) {
    int idx = blockIdx.x * 256 + threadIdx.x;   // 1024*32
    int b = idx & 31, o = idx >> 5;
    const float* w = Wt + (size_t)o * 512;
    float a0 = 0.f, a1 = 0.f, a2 = 0.f, a3 = 0.f;
#pragma unroll 4
    for (int i = 0; i < 512; i += 4) {
        a0 = fmaf(w[i],     g_d1[(i)     * 32 + b], a0);
        a1 = fmaf(w[i + 1], g_d1[(i + 1) * 32 + b], a1);
        a2 = fmaf(w[i + 2], g_d1[(i + 2) * 32 + b], a2);
        a3 = fmaf(w[i + 3], g_d1[(i + 3) * 32 + b], a3);
    }
    g_d2[o * 32 + b] = fmaxf(bias[o] + ((a0 + a1) + (a2 + a3)), 0.f);
}

__global__ void dec3_kernel(const float* __restrict__ Wt,
                            const float* __restrict__ bias,
                            float* __restrict__ out) {
    int idx = blockIdx.x * 256 + threadIdx.x;   // 784*32
    int b = idx & 31, o = idx >> 5;
    const float* w = Wt + (size_t)o * 1024;
    float a0 = 0.f, a1 = 0.f, a2 = 0.f, a3 = 0.f;
#pragma unroll 4
    for (int i = 0; i < 1024; i += 4) {
        a0 = fmaf(w[i],     g_d2[(i)     * 32 + b], a0);
        a1 = fmaf(w[i + 1], g_d2[(i + 1) * 32 + b], a1);
        a2 = fmaf(w[i + 2], g_d2[(i + 2) * 32 + b], a2);
        a3 = fmaf(w[i + 3], g_d2[(i + 3) * 32 + b], a3);
    }
    float x = bias[o] + ((a0 + a1) + (a2 + a3));
    out[OFF_RECON + (size_t)b * 784 + o] = 1.f / (1.f + expf(-x));
}

// ---------------------------------------------------------------------------
// Resolve inputs by (unique) element count — order-independent binding.
// ---------------------------------------------------------------------------
static const float* by_size(void* const* d_in, const int* s, int n, int want) {
    for (int i = 0; i < n; ++i)
        if (s[i] == want) return (const float*)d_in[i];
    return nullptr;
}

extern "C" void kernel_launch(void* const* d_in, const int* in_sizes, int n_in,
                              void* d_out, int out_size) {
    const float* x   = by_size(d_in, in_sizes, n_in, 32 * 784);        // 25088
    const float* cw  = by_size(d_in, in_sizes, n_in, 256 * 81);        // 20736
    const float* cb  = by_size(d_in, in_sizes, n_in, 256);
    const float* fcw = by_size(d_in, in_sizes, n_in, 943718400);       // 9216*102400
    const float* fcb = by_size(d_in, in_sizes, n_in, 9216);
    const float* W   = by_size(d_in, in_sizes, n_in, 1474560);         // 10*1152*16*8
    const float* d1w = by_size(d_in, in_sizes, n_in, 512 * 160);       // 81920
    const float* d1b = by_size(d_in, in_sizes, n_in, 512);
    const float* d2w = by_size(d_in, in_sizes, n_in, 1024 * 512);      // 524288
    const float* d2b = by_size(d_in, in_sizes, n_in, 1024);
    const float* d3w = by_size(d_in, in_sizes, n_in, 784 * 1024);      // 802816
    const float* d3b = by_size(d_in, in_sizes, n_in, 784);
    float* out = (float*)d_out;

    xT_kernel<<<98, 256>>>(x);
    conv_kernel<<<12800, 256>>>(cw, cb);                 // FIXED grid
    fc_gemm_kernel<<<dim3(36, 16), 128>>>(fcw);
    caps_kernel<<<144, 256>>>(fcb, out);
    uhat_kernel<<<1440, 256>>>(W);

    // routing iteration 0 (c = softmax(0) = 0.1 uniform)
    rout_sv_kernel<<<360, 512>>>(1);
    rout_squash_kernel<<<1, 320>>>(0, out);
    rout_update_kernel<<<1440, 256>>>(1);
    // routing iteration 1
    softmax_kernel<<<144, 256>>>(0, out);
    rout_sv_kernel<<<360, 512>>>(0);
    rout_squash_kernel<<<1, 320>>>(0, out);
    rout_update_kernel<<<1440, 256>>>(0);
    // final pass (emit c, b, digit caps)
    softmax_kernel<<<144, 256>>>(1, out);
    rout_sv_kernel<<<360, 512>>>(0);
    rout_squash_kernel<<<1, 320>>>(1, out);

    logits_kernel<<<1, 32>>>(out);
    dec1_kernel<<<64, 256>>>(d1w, d1b);
    dec2_kernel<<<128, 256>>>(d2w, d2b);
    dec3_kernel<<<98, 256>>>(d3w, d3b, out);
}

// round 7
// speedup vs baseline: 1.0578x; 1.0578x over previous
#include <cuda_runtime.h>
#include <math.h>

// ---------------------------------------------------------------------------
// CapsNet forward, B=32. Dominant cost: FC 102400->9216 (3.77 GB weights).
// Split-K GEMM using packed fp32 fma.rn.f32x2; weights streamed through a
// full-chunk double-buffered register pipeline (prefetch distance ~1000 cyc);
// activations via double-buffered broadcast-only smem tiles.
// ---------------------------------------------------------------------------

#define FC_M      9216
#define FC_K      102400
#define FC_SPLITK 16
#define FC_KSEG   6400      // FC_K / FC_SPLITK
#define FC_NCH    400       // FC_KSEG / 16  (even -> clean 2x unroll)

// output section offsets (concatenated tuple, fp32)
#define OFF_LOGITS 0
#define OFF_RECON  320
#define OFF_PRIM   25408
#define OFF_DIGIT  320320
#define OFF_C      325440
#define OFF_B      694080

// ---------------- device scratch (static; allocations are forbidden) -------
__device__ __align__(16) float g_xT[784 * 32];
__device__ __align__(16) float g_flatT[FC_K * 32];                 // 13.1 MB
__device__ __align__(16) float g_Cpart[FC_SPLITK * FC_M * 32];     // 18.9 MB
__device__ __align__(16) float g_capsT[FC_M * 32];
__device__ __align__(16) float g_uhatT[10 * 1152 * 16 * 32];       // 23.6 MB
__device__ __align__(16) float g_bT[10 * 1152 * 32];
__device__ __align__(16) float g_cT[10 * 1152 * 32];
__device__ __align__(16) float g_spart[10 * 36 * 16 * 32];
__device__ __align__(16) float g_v[10 * 32 * 16];
__device__ __align__(16) float g_masked[160 * 32];
__device__ __align__(16) float g_d1[512 * 32];
__device__ __align__(16) float g_d2[1024 * 32];

// ---------------- packed fp32 helpers (sm_100+) ----------------------------
__device__ __forceinline__ void fma2(unsigned long long& d,
                                     unsigned long long a,
                                     unsigned long long b) {
    asm("fma.rn.f32x2 %0, %1, %2, %0;" : "+l"(d) : "l"(a), "l"(b));
}
__device__ __forceinline__ unsigned long long dup2(float w) {
    unsigned long long r;
    asm("mov.b64 %0, {%1, %1};" : "=l"(r) : "f"(w));
    return r;
}
__device__ __forceinline__ float f4e(const float4& v, int e) {
    return e == 0 ? v.x : e == 1 ? v.y : e == 2 ? v.z : v.w;
}

// ---------------------------------------------------------------------------
// 0) x [32][784] -> xT [784][32]
// ---------------------------------------------------------------------------
__global__ void xT_kernel(const float* __restrict__ x) {
    int idx = blockIdx.x * 256 + threadIdx.x;
    if (idx < 784 * 32) {
        int b = idx / 784;
        int pix = idx - b * 784;
        g_xT[pix * 32 + b] = x[idx];
    }
}

// ---------------------------------------------------------------------------
// 1) conv 9x9 VALID + bias + relu -> flatT[k][b], k = oc*400 + oh*20 + ow
// ---------------------------------------------------------------------------
__global__ void conv_kernel(const float* __restrict__ cw,
                            const float* __restrict__ cb) {
    int idx = blockIdx.x * 256 + threadIdx.x;   // 3,276,800 threads
    int b = idx & 31;
    int k = idx >> 5;                            // 0 .. 102399
    int oc = k / 400;
    int pos = k - oc * 400;
    int oh = pos / 20;
    int ow = pos - oh * 20;
    float acc = cb[oc];
    const float* wp = cw + oc * 81;
#pragma unroll
    for (int r = 0; r < 9; ++r) {
#pragma unroll
        for (int cc = 0; cc < 9; ++cc) {
            acc = fmaf(g_xT[((oh + r) * 28 + ow + cc) * 32 + b], wp[r * 9 + cc], acc);
        }
    }
    g_flatT[(size_t)k * 32 + b] = fmaxf(acc, 0.f);
}

// ---------------------------------------------------------------------------
// tiny prep kernel (also shifts fc_gemm to app-launch #4 so ncu captures it)
// ---------------------------------------------------------------------------
__global__ void prep_kernel() {
    int t = threadIdx.x;                         // 256
    if (t < 160) {
        for (int b = 0; b < 32; ++b) g_v[(t / 16) * 512 + b * 16 + (t & 15)] = 0.f;
    }
}

// ---------------------------------------------------------------------------
// 2) FC GEMM: Cpart[sk][m][b] = sum_{k in seg} fc_w[m][k] * flatT[k][b]
//    128 threads; thread owns rows (t, t+128) x 32 b. Full-chunk (BK=16)
//    register weight double buffer; smem acts double-buffered, broadcast-only.
// ---------------------------------------------------------------------------
#define FC_COMPUTE(W0, W1, STAGE)                                            \
    _Pragma("unroll")                                                        \
    for (int g = 0; g < 4; ++g) {                                            \
        _Pragma("unroll")                                                    \
        for (int e = 0; e < 4; ++e) {                                        \
            const unsigned long long wd0 = dup2(f4e(W0[g], e));              \
            const unsigned long long wd1 = dup2(f4e(W1[g], e));              \
            _Pragma("unroll")                                                \
            for (int q = 0; q < 8; ++q) {                                    \
                const ulonglong2 ff =                                        \
                    *(const ulonglong2*)&fsh[STAGE][(g * 4 + e) * 8 + q];    \
                fma2(acc0[2 * q],     wd0, ff.x);                            \
                fma2(acc0[2 * q + 1], wd0, ff.y);                            \
                fma2(acc1[2 * q],     wd1, ff.x);                            \
                fma2(acc1[2 * q + 1], wd1, ff.y);                            \
            }                                                                \
        }                                                                    \
    }

__global__ void __launch_bounds__(128)
fc_gemm_kernel(const float* __restrict__ fcw) {
    __shared__ __align__(16) float4 fsh[2][128];  // [2 stages][16 k][32 b]

    const int t = threadIdx.x;
    const int mbase = blockIdx.x * 256;
    const long long kbase = (long long)blockIdx.y * FC_KSEG;
    const float4* fsrc = (const float4*)(g_flatT + kbase * 32);

    const float* wp0 = fcw + (size_t)(mbase + t) * FC_K + kbase;
    const float* wp1 = wp0 + (size_t)128 * FC_K;

    unsigned long long acc0[16], acc1[16];
#pragma unroll
    for (int i = 0; i < 16; ++i) { acc0[i] = 0ull; acc1[i] = 0ull; }

    float4 wA0[4], wA1[4], wB0[4], wB1[4];

    // prologue: chunk 0 weights + activations
#pragma unroll
    for (int g = 0; g < 4; ++g) {
        wA0[g] = *(const float4*)(wp0 + g * 4);
        wA1[g] = *(const float4*)(wp1 + g * 4);
    }
    fsh[0][t] = fsrc[t];
    __syncthreads();

#pragma unroll 1
    for (int c = 0; c < FC_NCH; c += 2) {
        // ---- stage A: compute chunk c, prefetch chunk c+1 ----
        {
            const float* p0 = wp0 + (size_t)(c + 1) * 16;
            const float* p1 = wp1 + (size_t)(c + 1) * 16;
#pragma unroll
            for (int g = 0; g < 4; ++g) {
                wB0[g] = *(const float4*)(p0 + g * 4);
                wB1[g] = *(const float4*)(p1 + g * 4);
            }
        }
        float4 fnext = fsrc[(size_t)(c + 1) * 128 + t];
        FC_COMPUTE(wA0, wA1, 0);
        fsh[1][t] = fnext;
        __syncthreads();

        // ---- stage B: compute chunk c+1, prefetch chunk c+2 ----
        const bool more = (c + 2) < FC_NCH;
        if (more) {
            const float* p0 = wp0 + (size_t)(c + 2) * 16;
            const float* p1 = wp1 + (size_t)(c + 2) * 16;
#pragma unroll
            for (int g = 0; g < 4; ++g) {
                wA0[g] = *(const float4*)(p0 + g * 4);
                wA1[g] = *(const float4*)(p1 + g * 4);
            }
            fnext = fsrc[(size_t)(c + 2) * 128 + t];
        }
        FC_COMPUTE(wB0, wB1, 1);
        if (more) fsh[0][t] = fnext;
        __syncthreads();
    }

    float* dst0 = g_Cpart + ((size_t)blockIdx.y * FC_M + mbase + t) * 32;
    float* dst1 = dst0 + (size_t)128 * 32;
#pragma unroll
    for (int q = 0; q < 8; ++q) {
        float2 a = *(float2*)&acc0[2 * q];
        float2 b = *(float2*)&acc0[2 * q + 1];
        *(float4*)(dst0 + q * 4) = make_float4(a.x, a.y, b.x, b.y);
        a = *(float2*)&acc1[2 * q];
        b = *(float2*)&acc1[2 * q + 1];
        *(float4*)(dst1 + q * 4) = make_float4(a.x, a.y, b.x, b.y);
    }
}

// ---------------------------------------------------------------------------
// 3) reduce split-K + bias + squash -> primary caps output + capsT scratch
// ---------------------------------------------------------------------------
__global__ void caps_kernel(const float* __restrict__ fcb,
                            float* __restrict__ out) {
    int idx = blockIdx.x * 256 + threadIdx.x;   // 36864
    int b = idx & 31;
    int cap = idx >> 5;
    float pc[8];
    float n2 = 0.f;
#pragma unroll
    for (int d = 0; d < 8; ++d) {
        int m = cap * 8 + d;
        float v = fcb[m];
#pragma unroll
        for (int s = 0; s < FC_SPLITK; ++s)
            v += g_Cpart[((size_t)s * FC_M + m) * 32 + b];
        pc[d] = v;
        n2 += v * v;
    }
    float scale = n2 / (1.f + n2);
    float inv = 1.f / sqrtf(n2);
#pragma unroll
    for (int d = 0; d < 8; ++d) {
        float o = scale * (pc[d] * inv + 1e-8f);
        out[OFF_PRIM + (size_t)b * 9216 + cap * 8 + d] = o;
        g_capsT[(cap * 8 + d) * 32 + b] = o;
    }
}

// ---------------------------------------------------------------------------
// 4) u_hat[b,n,p,d] = sum_i W[0,n,p,d,i] * caps[b,p,i] -> g_uhatT[n][p][d][b]
// ---------------------------------------------------------------------------
__global__ void uhat_kernel(const float* __restrict__ W) {
    int idx = blockIdx.x * 256 + threadIdx.x;   // 368640
    int b = idx & 31;
    int r = idx >> 5;                            // n*1152 + p
    int p = r % 1152;
    float caps[8];
#pragma unroll
    for (int i = 0; i < 8; ++i) caps[i] = g_capsT[(p * 8 + i) * 32 + b];
    const float* Wp = W + (size_t)r * 128;       // warp-uniform broadcast
    float* up = g_uhatT + (size_t)r * 512 + b;
#pragma unroll
    for (int d = 0; d < 16; ++d) {
        float a = 0.f;
#pragma unroll
        for (int i = 0; i < 8; ++i) a = fmaf(Wp[d * 8 + i], caps[i], a);
        up[d * 32] = a;
    }
}

// ---------------------------------------------------------------------------
// 5a) partial s sums over p-chunks of 32: spart[n][ch][d][b]
// ---------------------------------------------------------------------------
__global__ void rout_sv_kernel(int uniformC) {
    int n = blockIdx.x / 36;
    int ch = blockIdx.x - n * 36;
    int t = threadIdx.x;                         // 512 = 16 d * 32 b
    int b = t & 31;
    int d = t >> 5;
    int rbase = n * 1152 + ch * 32;
    float a = 0.f;
#pragma unroll 8
    for (int pp = 0; pp < 32; ++pp) {
        size_t r = rbase + pp;
        float c = uniformC ? 0.1f : g_cT[r * 32 + b];
        a = fmaf(c, g_uhatT[(r * 16 + d) * 32 + b], a);
    }
    g_spart[(((size_t)n * 36 + ch) * 16 + d) * 32 + b] = a;
}

// 5b) reduce partials + squash -> v (and digit caps output when final)
__global__ void rout_squash_kernel(int final_, float* __restrict__ out) {
    int t = threadIdx.x;                         // 320
    int b = t & 31;
    int n = t >> 5;
    float s[16];
    float n2 = 0.f;
#pragma unroll
    for (int d = 0; d < 16; ++d) {
        float a = 0.f;
        for (int ch = 0; ch < 36; ++ch)
            a += g_spart[(((size_t)n * 36 + ch) * 16 + d) * 32 + b];
        s[d] = a;
        n2 += a * a;
    }
    float scale = n2 / (1.f + n2);
    float inv = 1.f / sqrtf(n2);
#pragma unroll
    for (int d = 0; d < 16; ++d) {
        float v = scale * (s[d] * inv + 1e-8f);
        g_v[(n * 32 + b) * 16 + d] = v;
        if (final_) out[OFF_DIGIT + (size_t)b * 160 + n * 16 + d] = v;
    }
}

// 5c) b += sum_d u_hat * v   (first iteration: b = uv, since b starts at 0)
__global__ void rout_update_kernel(int first) {
    int idx = blockIdx.x * 256 + threadIdx.x;   // 368640
    int b = idx & 31;
    int r = idx >> 5;
    int n = r / 1152;
    const float* up = g_uhatT + (size_t)r * 512 + b;
    const float* vp = g_v + ((size_t)n * 32 + b) * 16;
    float a = 0.f;
#pragma unroll
    for (int d = 0; d < 16; ++d) a = fmaf(up[d * 32], vp[d], a);
    size_t o = (size_t)r * 32 + b;
    g_bT[o] = (first ? 0.f : g_bT[o]) + a;
}

// 5d) c = softmax over n of b; optionally emit final c and b to output
__global__ void softmax_kernel(int write_out, float* __restrict__ out) {
    int idx = blockIdx.x * 256 + threadIdx.x;   // 36864
    int b = idx & 31;
    int p = idx >> 5;
    float bv[10];
    float m = -1e30f;
#pragma unroll
    for (int n = 0; n < 10; ++n) {
        bv[n] = g_bT[((size_t)n * 1152 + p) * 32 + b];
        m = fmaxf(m, bv[n]);
    }
    float e[10];
    float sum = 0.f;
#pragma unroll
    for (int n = 0; n < 10; ++n) {
        e[n] = expf(bv[n] - m);
        sum += e[n];
    }
    float invs = 1.f / sum;
#pragma unroll
    for (int n = 0; n < 10; ++n) {
        float c = e[n] * invs;
        g_cT[((size_t)n * 1152 + p) * 32 + b] = c;
        if (write_out) {
            out[OFF_C + ((size_t)b * 10 + n) * 1152 + p] = c;
            out[OFF_B + ((size_t)b * 10 + n) * 1152 + p] = bv[n];
        }
    }
}

// ---------------------------------------------------------------------------
// 6) logits = ||digit||, argmax (first max), masked -> g_masked[i][b]
// ---------------------------------------------------------------------------
__global__ void logits_kernel(float* __restrict__ out) {
    int b = threadIdx.x;                         // 32
    float dg[160];
    for (int i = 0; i < 160; ++i) dg[i] = out[OFF_DIGIT + (size_t)b * 160 + i];
    float best = -1.f;
    int am = 0;
    for (int n = 0; n < 10; ++n) {
        float n2 = 0.f;
        for (int d = 0; d < 16; ++d) {
            float v = dg[n * 16 + d];
            n2 += v * v;
        }
        float lg = sqrtf(n2);
        out[OFF_LOGITS + b * 10 + n] = lg;
        if (lg > best) { best = lg; am = n; }
    }
    for (int n = 0; n < 10; ++n)
        for (int d = 0; d < 16; ++d)
            g_masked[(n * 16 + d) * 32 + b] = (n == am) ? dg[n * 16 + d] : 0.f;
}

// ---------------------------------------------------------------------------
// 7) decoder MLP
// ---------------------------------------------------------------------------
__global__ void dec1_kernel(const float* __restrict__ Wt,
                            const float* __restrict__ bias) {
    int idx = blockIdx.x * 256 + threadIdx.x;   // 512*32
    int b = idx & 31, o = idx >> 5;
    const float* w = Wt + (size_t)o * 160;
    float a0 = 0.f, a1 = 0.f, a2 = 0.f, a3 = 0.f;
#pragma unroll 4
    for (int i = 0; i < 160; i += 4) {
        a0 = fmaf(w[i],     g_masked[(i)     * 32 + b], a0);
        a1 = fmaf(w[i + 1], g_masked[(i + 1) * 32 + b], a1);
        a2 = fmaf(w[i + 2], g_masked[(i + 2) * 32 + b], a2);
        a3 = fmaf(w[i + 3], g_masked[(i + 3) * 32 + b], a3);
    }
    g_d1[o * 32 + b] = fmaxf(bias[o] + ((a0 + a1) + (a2 + a3)), 0.f);
}

__global__ void dec2_kernel(const float* __restrict__ Wt,
                            const float* __restrict__ bias) {
    int idx = blockIdx.x * 256 + threadIdx.x;   // 1024*32
    int b = idx & 31, o = idx >> 5;
    const float* w = Wt + (size_t)o * 512;
    float a0 = 0.f, a1 = 0.f, a2 = 0.f, a3 = 0.f;
#pragma unroll 4
    for (int i = 0; i < 512; i += 4) {
        a0 = fmaf(w[i],     g_d1[(i)     * 32 + b], a0);
        a1 = fmaf(w[i + 1], g_d1[(i + 1) * 32 + b], a1);
        a2 = fmaf(w[i + 2], g_d1[(i + 2) * 32 + b], a2);
        a3 = fmaf(w[i + 3], g_d1[(i + 3) * 32 + b], a3);
    }
    g_d2[o * 32 + b] = fmaxf(bias[o] + ((a0 + a1) + (a2 + a3)), 0.f);
}

__global__ void dec3_kernel(const float* __restrict__ Wt,
                            const float* __restrict__ bias,
                            float* __restrict__ out) {
    int idx = blockIdx.x * 256 + threadIdx.x;   // 784*32
    int b = idx & 31, o = idx >> 5;
    const float* w = Wt + (size_t)o * 1024;
    float a0 = 0.f, a1 = 0.f, a2 = 0.f, a3 = 0.f;
#pragma unroll 4
    for (int i = 0; i < 1024; i += 4) {
        a0 = fmaf(w[i],     g_d2[(i)     * 32 + b], a0);
        a1 = fmaf(w[i + 1], g_d2[(i + 1) * 32 + b], a1);
        a2 = fmaf(w[i + 2], g_d2[(i + 2) * 32 + b], a2);
        a3 = fmaf(w[i + 3], g_d2[(i + 3) * 32 + b], a3);
    }
    float x = bias[o] + ((a0 + a1) + (a2 + a3));
    out[OFF_RECON + (size_t)b * 784 + o] = 1.f / (1.f + expf(-x));
}

// ---------------------------------------------------------------------------
// Resolve inputs by (unique) element count — order-independent binding.
// ---------------------------------------------------------------------------
static const float* by_size(void* const* d_in, const int* s, int n, int want) {
    for (int i = 0; i < n; ++i)
        if (s[i] == want) return (const float*)d_in[i];
    return nullptr;
}

extern "C" void kernel_launch(void* const* d_in, const int* in_sizes, int n_in,
                              void* d_out, int out_size) {
    const float* x   = by_size(d_in, in_sizes, n_in, 32 * 784);        // 25088
    const float* cw  = by_size(d_in, in_sizes, n_in, 256 * 81);        // 20736
    const float* cb  = by_size(d_in, in_sizes, n_in, 256);
    const float* fcw = by_size(d_in, in_sizes, n_in, 943718400);       // 9216*102400
    const float* fcb = by_size(d_in, in_sizes, n_in, 9216);
    const float* W   = by_size(d_in, in_sizes, n_in, 1474560);         // 10*1152*16*8
    const float* d1w = by_size(d_in, in_sizes, n_in, 512 * 160);       // 81920
    const float* d1b = by_size(d_in, in_sizes, n_in, 512);
    const float* d2w = by_size(d_in, in_sizes, n_in, 1024 * 512);      // 524288
    const float* d2b = by_size(d_in, in_sizes, n_in, 1024);
    const float* d3w = by_size(d_in, in_sizes, n_in, 784 * 1024);      // 802816
    const float* d3b = by_size(d_in, in_sizes, n_in, 784);
    float* out = (float*)d_out;

    xT_kernel<<<98, 256>>>(x);                           // launch 1
    conv_kernel<<<12800, 256>>>(cw, cb);                 // launch 2
    prep_kernel<<<1, 256>>>();                           // launch 3 (shifts fc to #4)
    fc_gemm_kernel<<<dim3(36, 16), 128>>>(fcw);          // launch 4  <- ncu slot
    caps_kernel<<<144, 256>>>(fcb, out);
    uhat_kernel<<<1440, 256>>>(W);

    // routing iteration 0 (c = softmax(0) = 0.1 uniform)
    rout_sv_kernel<<<360, 512>>>(1);
    rout_squash_kernel<<<1, 320>>>(0, out);
    rout_update_kernel<<<1440, 256>>>(1);
    // routing iteration 1
    softmax_kernel<<<144, 256>>>(0, out);
    rout_sv_kernel<<<360, 512>>>(0);
    rout_squash_kernel<<<1, 320>>>(0, out);
    rout_update_kernel<<<1440, 256>>>(0);
    // final pass (emit c, b, digit caps)
    softmax_kernel<<<144, 256>>>(1, out);
    rout_sv_kernel<<<360, 512>>>(0);
    rout_squash_kernel<<<1, 320>>>(1, out);

    logits_kernel<<<1, 32>>>(out);
    dec1_kernel<<<64, 256>>>(d1w, d1b);
    dec2_kernel<<<128, 256>>>(d2w, d2b);
    dec3_kernel<<<98, 256>>>(d3w, d3b, out);
}

// round 8
// speedup vs baseline: 1.1736x; 1.1094x over previous
#include <cuda_runtime.h>
#include <math.h>

// ---------------------------------------------------------------------------
// CapsNet forward, B=32. Dominant cost: FC 102400->9216 (3.77 GB weights).
// Split-K GEMM with smem-staged, k-coalesced weight tiles (fixes the L1tex
// wavefront storm seen in R7 ncu: row-per-lane LDG = 32 sectors/instr).
// Compute uses packed fp32 fma.rn.f32x2.
// ---------------------------------------------------------------------------

#define FC_M      9216
#define FC_K      102400
#define FC_SPLITK 16
#define FC_KSEG   6400      // FC_K / FC_SPLITK
#define FC_BK     32
#define FC_BM     256
#define FC_NT     200       // FC_KSEG / FC_BK

// output section offsets (concatenated tuple, fp32)
#define OFF_LOGITS 0
#define OFF_RECON  320
#define OFF_PRIM   25408
#define OFF_DIGIT  320320
#define OFF_C      325440
#define OFF_B      694080

// ---------------- device scratch (static; allocations are forbidden) -------
__device__ __align__(16) float g_xT[784 * 32];
__device__ __align__(16) float g_flatT[FC_K * 32];                 // 13.1 MB
__device__ __align__(16) float g_Cpart[FC_SPLITK * FC_M * 32];     // 18.9 MB
__device__ __align__(16) float g_capsT[FC_M * 32];
__device__ __align__(16) float g_uhatT[10 * 1152 * 16 * 32];       // 23.6 MB
__device__ __align__(16) float g_bT[10 * 1152 * 32];
__device__ __align__(16) float g_cT[10 * 1152 * 32];
__device__ __align__(16) float g_spart[10 * 36 * 16 * 32];
__device__ __align__(16) float g_v[10 * 32 * 16];
__device__ __align__(16) float g_masked[160 * 32];
__device__ __align__(16) float g_d1[512 * 32];
__device__ __align__(16) float g_d2[1024 * 32];

// ---------------- packed fp32 helpers (sm_100+) ----------------------------
__device__ __forceinline__ void fma2(unsigned long long& d,
                                     unsigned long long a,
                                     unsigned long long b) {
    asm("fma.rn.f32x2 %0, %1, %2, %0;" : "+l"(d) : "l"(a), "l"(b));
}
__device__ __forceinline__ unsigned long long dup2(float w) {
    unsigned long long r;
    asm("mov.b64 %0, {%1, %1};" : "=l"(r) : "f"(w));
    return r;
}
__device__ __forceinline__ float f4e(const float4& v, int e) {
    return e == 0 ? v.x : e == 1 ? v.y : e == 2 ? v.z : v.w;
}

// ---------------------------------------------------------------------------
// 0) x [32][784] -> xT [784][32]
// ---------------------------------------------------------------------------
__global__ void xT_kernel(const float* __restrict__ x) {
    int idx = blockIdx.x * 256 + threadIdx.x;
    if (idx < 784 * 32) {
        int b = idx / 784;
        int pix = idx - b * 784;
        g_xT[pix * 32 + b] = x[idx];
    }
}

// ---------------------------------------------------------------------------
// 1) conv 9x9 VALID + bias + relu -> flatT[k][b], k = oc*400 + oh*20 + ow
// ---------------------------------------------------------------------------
__global__ void conv_kernel(const float* __restrict__ cw,
                            const float* __restrict__ cb) {
    int idx = blockIdx.x * 256 + threadIdx.x;   // 3,276,800 threads
    int b = idx & 31;
    int k = idx >> 5;                            // 0 .. 102399
    int oc = k / 400;
    int pos = k - oc * 400;
    int oh = pos / 20;
    int ow = pos - oh * 20;
    float acc = cb[oc];
    const float* wp = cw + oc * 81;
#pragma unroll
    for (int r = 0; r < 9; ++r) {
#pragma unroll
        for (int cc = 0; cc < 9; ++cc) {
            acc = fmaf(g_xT[((oh + r) * 28 + ow + cc) * 32 + b], wp[r * 9 + cc], acc);
        }
    }
    g_flatT[(size_t)k * 32 + b] = fmaxf(acc, 0.f);
}

// ---------------------------------------------------------------------------
// tiny prep kernel (keeps fc_gemm at app-launch #4 = the ncu capture slot)
// ---------------------------------------------------------------------------
__global__ void prep_kernel() {
    int t = threadIdx.x;                         // 256
    if (t < 160) {
        for (int b = 0; b < 32; ++b) g_v[(t / 16) * 512 + b * 16 + (t & 15)] = 0.f;
    }
}

// ---------------------------------------------------------------------------
// 2) FC GEMM: Cpart[sk][m][b] = sum_{k in seg} fc_w[m][k] * flatT[k][b]
//    256 threads, BM=256, BK=32, double-buffered smem for BOTH operands.
//    Weight tile stored transposed [k][m] (pad 260) so:
//      - global loads are k-coalesced (lanes sweep k within a row),
//      - compute-side LDS.128 over 4 consecutive rows is conflict-free.
//    Thread computes 4 rows x 8 batches = 16 u64 f32x2 accumulators.
// ---------------------------------------------------------------------------
__global__ void __launch_bounds__(256, 2)
fc_gemm_kernel(const float* __restrict__ fcw) {
    __shared__ __align__(16) float wsh[2][FC_BK][260];  // 66.6 KB
    __shared__ __align__(16) float ash[2][FC_BK][32];   //  8   KB

    const int t = threadIdx.x;
    const int mbase = blockIdx.x * FC_BM;
    const long long kbase = (long long)blockIdx.y * FC_KSEG;

    // loader mapping: float4 index i = t + j*256 (j=0..7):
    //   row = (i>>3) = (t>>3) + j*32, kgroup = i&7 = t&7
    const int lrow = t >> 3;                 // 0..31
    const int lkg  = t & 7;                  // 0..7
    const float* wsrc = fcw + (size_t)(mbase + lrow) * FC_K + kbase + lkg * 4;
    const size_t wjstride = (size_t)32 * FC_K;        // +32 rows
    const float4* asrc = (const float4*)(g_flatT + kbase * 32);

    // compute mapping: 4 consecutive rows x 8 batches
    const int mg = t >> 2;                   // 0..63 -> rows mg*4..mg*4+3
    const int bg = t & 3;                    // 0..3  -> batches bg*8..bg*8+7

    unsigned long long acc[4][4];
#pragma unroll
    for (int r = 0; r < 4; ++r)
#pragma unroll
        for (int q = 0; q < 4; ++q) acc[r][q] = 0ull;

    float4 wreg[8];
    float4 areg;

    // ---- prologue: load + stage tile 0 ----
#pragma unroll
    for (int j = 0; j < 8; ++j)
        wreg[j] = *(const float4*)(wsrc + j * wjstride);
    areg = asrc[t];
#pragma unroll
    for (int j = 0; j < 8; ++j) {
#pragma unroll
        for (int e = 0; e < 4; ++e)
            wsh[0][lkg * 4 + e][lrow + j * 32] = f4e(wreg[j], e);
    }
    ((float4*)&ash[0][0][0])[t] = areg;
    __syncthreads();

#pragma unroll 1
    for (int c = 0; c < FC_NT; ++c) {
        const int buf = c & 1;
        const bool more = (c + 1) < FC_NT;
        if (more) {
            const float* wp = wsrc + (size_t)(c + 1) * FC_BK;
#pragma unroll
            for (int j = 0; j < 8; ++j)
                wreg[j] = *(const float4*)(wp + j * wjstride);
            areg = asrc[(size_t)(c + 1) * 256 + t];
        }

        // ---- compute 32 k on buffer `buf` ----
#pragma unroll 8
        for (int k = 0; k < FC_BK; ++k) {
            const float4 w4 = *(const float4*)&wsh[buf][k][mg * 4];
            const unsigned long long wd0 = dup2(w4.x);
            const unsigned long long wd1 = dup2(w4.y);
            const unsigned long long wd2 = dup2(w4.z);
            const unsigned long long wd3 = dup2(w4.w);
            const ulonglong2 f0 = *(const ulonglong2*)&ash[buf][k][bg * 8];
            const ulonglong2 f1 = *(const ulonglong2*)&ash[buf][k][bg * 8 + 4];
            fma2(acc[0][0], wd0, f0.x); fma2(acc[0][1], wd0, f0.y);
            fma2(acc[0][2], wd0, f1.x); fma2(acc[0][3], wd0, f1.y);
            fma2(acc[1][0], wd1, f0.x); fma2(acc[1][1], wd1, f0.y);
            fma2(acc[1][2], wd1, f1.x); fma2(acc[1][3], wd1, f1.y);
            fma2(acc[2][0], wd2, f0.x); fma2(acc[2][1], wd2, f0.y);
            fma2(acc[2][2], wd2, f1.x); fma2(acc[2][3], wd2, f1.y);
            fma2(acc[3][0], wd3, f0.x); fma2(acc[3][1], wd3, f0.y);
            fma2(acc[3][2], wd3, f1.x); fma2(acc[3][3], wd3, f1.y);
        }

        if (more) {
            const int nb = buf ^ 1;
#pragma unroll
            for (int j = 0; j < 8; ++j) {
#pragma unroll
                for (int e = 0; e < 4; ++e)
                    wsh[nb][lkg * 4 + e][lrow + j * 32] = f4e(wreg[j], e);
            }
            ((float4*)&ash[nb][0][0])[t] = areg;
        }
        __syncthreads();
    }

    // ---- epilogue: rows mbase + mg*4 + r, batches bg*8..+7 ----
#pragma unroll
    for (int r = 0; r < 4; ++r) {
        float* dst = g_Cpart +
            ((size_t)blockIdx.y * FC_M + mbase + mg * 4 + r) * 32 + bg * 8;
        float2 p0 = *(float2*)&acc[r][0];
        float2 p1 = *(float2*)&acc[r][1];
        float2 p2 = *(float2*)&acc[r][2];
        float2 p3 = *(float2*)&acc[r][3];
        *(float4*)(dst)     = make_float4(p0.x, p0.y, p1.x, p1.y);
        *(float4*)(dst + 4) = make_float4(p2.x, p2.y, p3.x, p3.y);
    }
}

// ---------------------------------------------------------------------------
// 3) reduce split-K + bias + squash -> primary caps output + capsT scratch
// ---------------------------------------------------------------------------
__global__ void caps_kernel(const float* __restrict__ fcb,
                            float* __restrict__ out) {
    int idx = blockIdx.x * 256 + threadIdx.x;   // 36864
    int b = idx & 31;
    int cap = idx >> 5;
    float pc[8];
    float n2 = 0.f;
#pragma unroll
    for (int d = 0; d < 8; ++d) {
        int m = cap * 8 + d;
        float v = fcb[m];
#pragma unroll
        for (int s = 0; s < FC_SPLITK; ++s)
            v += g_Cpart[((size_t)s * FC_M + m) * 32 + b];
        pc[d] = v;
        n2 += v * v;
    }
    float scale = n2 / (1.f + n2);
    float inv = 1.f / sqrtf(n2);
#pragma unroll
    for (int d = 0; d < 8; ++d) {
        float o = scale * (pc[d] * inv + 1e-8f);
        out[OFF_PRIM + (size_t)b * 9216 + cap * 8 + d] = o;
        g_capsT[(cap * 8 + d) * 32 + b] = o;
    }
}

// ---------------------------------------------------------------------------
// 4) u_hat[b,n,p,d] = sum_i W[0,n,p,d,i] * caps[b,p,i] -> g_uhatT[n][p][d][b]
// ---------------------------------------------------------------------------
__global__ void uhat_kernel(const float* __restrict__ W) {
    int idx = blockIdx.x * 256 + threadIdx.x;   // 368640
    int b = idx & 31;
    int r = idx >> 5;                            // n*1152 + p
    int p = r % 1152;
    float caps[8];
#pragma unroll
    for (int i = 0; i < 8; ++i) caps[i] = g_capsT[(p * 8 + i) * 32 + b];
    const float* Wp = W + (size_t)r * 128;       // warp-uniform broadcast
    float* up = g_uhatT + (size_t)r * 512 + b;
#pragma unroll
    for (int d = 0; d < 16; ++d) {
        float a = 0.f;
#pragma unroll
        for (int i = 0; i < 8; ++i) a = fmaf(Wp[d * 8 + i], caps[i], a);
        up[d * 32] = a;
    }
}

// ---------------------------------------------------------------------------
// 5a) partial s sums over p-chunks of 32: spart[n][ch][d][b]
// ---------------------------------------------------------------------------
__global__ void rout_sv_kernel(int uniformC) {
    int n = blockIdx.x / 36;
    int ch = blockIdx.x - n * 36;
    int t = threadIdx.x;                         // 512 = 16 d * 32 b
    int b = t & 31;
    int d = t >> 5;
    int rbase = n * 1152 + ch * 32;
    float a = 0.f;
#pragma unroll 8
    for (int pp = 0; pp < 32; ++pp) {
        size_t r = rbase + pp;
        float c = uniformC ? 0.1f : g_cT[r * 32 + b];
        a = fmaf(c, g_uhatT[(r * 16 + d) * 32 + b], a);
    }
    g_spart[(((size_t)n * 36 + ch) * 16 + d) * 32 + b] = a;
}

// 5b) reduce partials + squash -> v (and digit caps output when final)
__global__ void rout_squash_kernel(int final_, float* __restrict__ out) {
    int t = threadIdx.x;                         // 320
    int b = t & 31;
    int n = t >> 5;
    float s[16];
    float n2 = 0.f;
#pragma unroll
    for (int d = 0; d < 16; ++d) {
        float a = 0.f;
        for (int ch = 0; ch < 36; ++ch)
            a += g_spart[(((size_t)n * 36 + ch) * 16 + d) * 32 + b];
        s[d] = a;
        n2 += a * a;
    }
    float scale = n2 / (1.f + n2);
    float inv = 1.f / sqrtf(n2);
#pragma unroll
    for (int d = 0; d < 16; ++d) {
        float v = scale * (s[d] * inv + 1e-8f);
        g_v[(n * 32 + b) * 16 + d] = v;
        if (final_) out[OFF_DIGIT + (size_t)b * 160 + n * 16 + d] = v;
    }
}

// 5c) b += sum_d u_hat * v   (first iteration: b = uv, since b starts at 0)
__global__ void rout_update_kernel(int first) {
    int idx = blockIdx.x * 256 + threadIdx.x;   // 368640
    int b = idx & 31;
    int r = idx >> 5;
    int n = r / 1152;
    const float* up = g_uhatT + (size_t)r * 512 + b;
    const float* vp = g_v + ((size_t)n * 32 + b) * 16;
    float a = 0.f;
#pragma unroll
    for (int d = 0; d < 16; ++d) a = fmaf(up[d * 32], vp[d], a);
    size_t o = (size_t)r * 32 + b;
    g_bT[o] = (first ? 0.f : g_bT[o]) + a;
}

// 5d) c = softmax over n of b; optionally emit final c and b to output
__global__ void softmax_kernel(int write_out, float* __restrict__ out) {
    int idx = blockIdx.x * 256 + threadIdx.x;   // 36864
    int b = idx & 31;
    int p = idx >> 5;
    float bv[10];
    float m = -1e30f;
#pragma unroll
    for (int n = 0; n < 10; ++n) {
        bv[n] = g_bT[((size_t)n * 1152 + p) * 32 + b];
        m = fmaxf(m, bv[n]);
    }
    float e[10];
    float sum = 0.f;
#pragma unroll
    for (int n = 0; n < 10; ++n) {
        e[n] = expf(bv[n] - m);
        sum += e[n];
    }
    float invs = 1.f / sum;
#pragma unroll
    for (int n = 0; n < 10; ++n) {
        float c = e[n] * invs;
        g_cT[((size_t)n * 1152 + p) * 32 + b] = c;
        if (write_out) {
            out[OFF_C + ((size_t)b * 10 + n) * 1152 + p] = c;
            out[OFF_B + ((size_t)b * 10 + n) * 1152 + p] = bv[n];
        }
    }
}

// ---------------------------------------------------------------------------
// 6) logits = ||digit||, argmax (first max), masked -> g_masked[i][b]
// ---------------------------------------------------------------------------
__global__ void logits_kernel(float* __restrict__ out) {
    int b = threadIdx.x;                         // 32
    float dg[160];
    for (int i = 0; i < 160; ++i) dg[i] = out[OFF_DIGIT + (size_t)b * 160 + i];
    float best = -1.f;
    int am = 0;
    for (int n = 0; n < 10; ++n) {
        float n2 = 0.f;
        for (int d = 0; d < 16; ++d) {
            float v = dg[n * 16 + d];
            n2 += v * v;
        }
        float lg = sqrtf(n2);
        out[OFF_LOGITS + b * 10 + n] = lg;
        if (lg > best) { best = lg; am = n; }
    }
    for (int n = 0; n < 10; ++n)
        for (int d = 0; d < 16; ++d)
            g_masked[(n * 16 + d) * 32 + b] = (n == am) ? dg[n * 16 + d] : 0.f;
}

// ---------------------------------------------------------------------------
// 7) decoder MLP
// ---------------------------------------------------------------------------
__global__ void dec1_kernel(const float* __restrict__ Wt,
                            const float* __restrict__ bias) {
    int idx = blockIdx.x * 256 + threadIdx.x;   // 512*32
    int b = idx & 31, o = idx >> 5;
    const float* w = Wt + (size_t)o * 160;
    float a0 = 0.f, a1 = 0.f, a2 = 0.f, a3 = 0.f;
#pragma unroll 4
    for (int i = 0; i < 160; i += 4) {
        a0 = fmaf(w[i],     g_masked[(i)     * 32 + b], a0);
        a1 = fmaf(w[i + 1], g_masked[(i + 1) * 32 + b], a1);
        a2 = fmaf(w[i + 2], g_masked[(i + 2) * 32 + b], a2);
        a3 = fmaf(w[i + 3], g_masked[(i + 3) * 32 + b], a3);
    }
    g_d1[o * 32 + b] = fmaxf(bias[o] + ((a0 + a1) + (a2 + a3)), 0.f);
}

__global__ void dec2_kernel(const float* __restrict__ Wt,
                            const float* __restrict__ bias) {
    int idx = blockIdx.x * 256 + threadIdx.x;   // 1024*32
    int b = idx & 31, o = idx >> 5;
    const float* w = Wt + (size_t)o * 512;
    float a0 = 0.f, a1 = 0.f, a2 = 0.f, a3 = 0.f;
#pragma unroll 4
    for (int i = 0; i < 512; i += 4) {
        a0 = fmaf(w[i],     g_d1[(i)     * 32 + b], a0);
        a1 = fmaf(w[i + 1], g_d1[(i + 1) * 32 + b], a1);
        a2 = fmaf(w[i + 2], g_d1[(i + 2) * 32 + b], a2);
        a3 = fmaf(w[i + 3], g_d1[(i + 3) * 32 + b], a3);
    }
    g_d2[o * 32 + b] = fmaxf(bias[o] + ((a0 + a1) + (a2 + a3)), 0.f);
}

__global__ void dec3_kernel(const float* __restrict__ Wt,
                            const float* __restrict__ bias,
                            float* __restrict__ out) {
    int idx = blockIdx.x * 256 + threadIdx.x;   // 784*32
    int b = idx & 31, o = idx >> 5;
    const float* w = Wt + (size_t)o * 1024;
    float a0 = 0.f, a1 = 0.f, a2 = 0.f, a3 = 0.f;
#pragma unroll 4
    for (int i = 0; i < 1024; i += 4) {
        a0 = fmaf(w[i],     g_d2[(i)     * 32 + b], a0);
        a1 = fmaf(w[i + 1], g_d2[(i + 1) * 32 + b], a1);
        a2 = fmaf(w[i + 2], g_d2[(i + 2) * 32 + b], a2);
        a3 = fmaf(w[i + 3], g_d2[(i + 3) * 32 + b], a3);
    }
    float x = bias[o] + ((a0 + a1) + (a2 + a3));
    out[OFF_RECON + (size_t)b * 784 + o] = 1.f / (1.f + expf(-x));
}

// ---------------------------------------------------------------------------
// Resolve inputs by (unique) element count — order-independent binding.
// ---------------------------------------------------------------------------
static const float* by_size(void* const* d_in, const int* s, int n, int want) {
    for (int i = 0; i < n; ++i)
        if (s[i] == want) return (const float*)d_in[i];
    return nullptr;
}

extern "C" void kernel_launch(void* const* d_in, const int* in_sizes, int n_in,
                              void* d_out, int out_size) {
    const float* x   = by_size(d_in, in_sizes, n_in, 32 * 784);        // 25088
    const float* cw  = by_size(d_in, in_sizes, n_in, 256 * 81);        // 20736
    const float* cb  = by_size(d_in, in_sizes, n_in, 256);
    const float* fcw = by_size(d_in, in_sizes, n_in, 943718400);       // 9216*102400
    const float* fcb = by_size(d_in, in_sizes, n_in, 9216);
    const float* W   = by_size(d_in, in_sizes, n_in, 1474560);         // 10*1152*16*8
    const float* d1w = by_size(d_in, in_sizes, n_in, 512 * 160);       // 81920
    const float* d1b = by_size(d_in, in_sizes, n_in, 512);
    const float* d2w = by_size(d_in, in_sizes, n_in, 1024 * 512);      // 524288
    const float* d2b = by_size(d_in, in_sizes, n_in, 1024);
    const float* d3w = by_size(d_in, in_sizes, n_in, 784 * 1024);      // 802816
    const float* d3b = by_size(d_in, in_sizes, n_in, 784);
    float* out = (float*)d_out;

    xT_kernel<<<98, 256>>>(x);                           // launch 1
    conv_kernel<<<12800, 256>>>(cw, cb);                 // launch 2
    prep_kernel<<<1, 256>>>();                           // launch 3
    fc_gemm_kernel<<<dim3(36, 16), 256>>>(fcw);          // launch 4 <- ncu slot
    caps_kernel<<<144, 256>>>(fcb, out);
    uhat_kernel<<<1440, 256>>>(W);

    // routing iteration 0 (c = softmax(0) = 0.1 uniform)
    rout_sv_kernel<<<360, 512>>>(1);
    rout_squash_kernel<<<1, 320>>>(0, out);
    rout_update_kernel<<<1440, 256>>>(1);
    // routing iteration 1
    softmax_kernel<<<144, 256>>>(0, out);
    rout_sv_kernel<<<360, 512>>>(0);
    rout_squash_kernel<<<1, 320>>>(0, out);
    rout_update_kernel<<<1440, 256>>>(0);
    // final pass (emit c, b, digit caps)
    softmax_kernel<<<144, 256>>>(1, out);
    rout_sv_kernel<<<360, 512>>>(0);
    rout_squash_kernel<<<1, 320>>>(1, out);

    logits_kernel<<<1, 32>>>(out);
    dec1_kernel<<<64, 256>>>(d1w, d1b);
    dec2_kernel<<<128, 256>>>(d2w, d2b);
    dec3_kernel<<<98, 256>>>(d3w, d3b, out);
}

// round 9
// speedup vs baseline: 1.3263x; 1.1301x over previous
#include <cuda_runtime.h>
#include <math.h>

// ---------------------------------------------------------------------------
// CapsNet forward, B=32. Dominant cost: FC 102400->9216 (3.77 GB weights).
// Split-K GEMM, smem-staged k-coalesced weight tiles with XOR-swizzled
// [k][256] layout (R8's 16-way STS bank conflict eliminated).
// Compute uses packed fp32 fma.rn.f32x2.
// ---------------------------------------------------------------------------

#define FC_M      9216
#define FC_K      102400
#define FC_SPLITK 16
#define FC_KSEG   6400      // FC_K / FC_SPLITK
#define FC_BK     32
#define FC_BM     256
#define FC_NT     200       // FC_KSEG / FC_BK

// output section offsets (concatenated tuple, fp32)
#define OFF_LOGITS 0
#define OFF_RECON  320
#define OFF_PRIM   25408
#define OFF_DIGIT  320320
#define OFF_C      325440
#define OFF_B      694080

// ---------------- device scratch (static; allocations are forbidden) -------
__device__ __align__(16) float g_xT[784 * 32];
__device__ __align__(16) float g_flatT[FC_K * 32];                 // 13.1 MB
__device__ __align__(16) float g_Cpart[FC_SPLITK * FC_M * 32];     // 18.9 MB
__device__ __align__(16) float g_capsT[FC_M * 32];
__device__ __align__(16) float g_uhatT[10 * 1152 * 16 * 32];       // 23.6 MB
__device__ __align__(16) float g_bT[10 * 1152 * 32];
__device__ __align__(16) float g_cT[10 * 1152 * 32];
__device__ __align__(16) float g_spart[10 * 36 * 16 * 32];
__device__ __align__(16) float g_v[10 * 32 * 16];
__device__ __align__(16) float g_masked[160 * 32];
__device__ __align__(16) float g_d1[512 * 32];
__device__ __align__(16) float g_d2[1024 * 32];

// ---------------- packed fp32 helpers (sm_100+) ----------------------------
__device__ __forceinline__ void fma2(unsigned long long& d,
                                     unsigned long long a,
                                     unsigned long long b) {
    asm("fma.rn.f32x2 %0, %1, %2, %0;" : "+l"(d) : "l"(a), "l"(b));
}
__device__ __forceinline__ unsigned long long dup2(float w) {
    unsigned long long r;
    asm("mov.b64 %0, {%1, %1};" : "=l"(r) : "f"(w));
    return r;
}
__device__ __forceinline__ float f4e(const float4& v, int e) {
    return e == 0 ? v.x : e == 1 ? v.y : e == 2 ? v.z : v.w;
}

// ---------------------------------------------------------------------------
// 0) x [32][784] -> xT [784][32]
// ---------------------------------------------------------------------------
__global__ void xT_kernel(const float* __restrict__ x) {
    int idx = blockIdx.x * 256 + threadIdx.x;
    if (idx < 784 * 32) {
        int b = idx / 784;
        int pix = idx - b * 784;
        g_xT[pix * 32 + b] = x[idx];
    }
}

// ---------------------------------------------------------------------------
// 1) conv 9x9 VALID + bias + relu -> flatT[k][b], k = oc*400 + oh*20 + ow
// ---------------------------------------------------------------------------
__global__ void conv_kernel(const float* __restrict__ cw,
                            const float* __restrict__ cb) {
    int idx = blockIdx.x * 256 + threadIdx.x;   // 3,276,800 threads
    int b = idx & 31;
    int k = idx >> 5;                            // 0 .. 102399
    int oc = k / 400;
    int pos = k - oc * 400;
    int oh = pos / 20;
    int ow = pos - oh * 20;
    float acc = cb[oc];
    const float* wp = cw + oc * 81;
#pragma unroll
    for (int r = 0; r < 9; ++r) {
#pragma unroll
        for (int cc = 0; cc < 9; ++cc) {
            acc = fmaf(g_xT[((oh + r) * 28 + ow + cc) * 32 + b], wp[r * 9 + cc], acc);
        }
    }
    g_flatT[(size_t)k * 32 + b] = fmaxf(acc, 0.f);
}

// ---------------------------------------------------------------------------
// tiny prep kernel (keeps fc_gemm at app-launch #4 = the ncu capture slot)
// ---------------------------------------------------------------------------
__global__ void prep_kernel() {
    int t = threadIdx.x;                         // 256
    if (t < 160) {
        for (int b = 0; b < 32; ++b) g_v[(t / 16) * 512 + b * 16 + (t & 15)] = 0.f;
    }
}

// ---------------------------------------------------------------------------
// 2) FC GEMM: Cpart[sk][m][b] = sum_{k in seg} fc_w[m][k] * flatT[k][b]
//    256 threads, BM=256, BK=32, double-buffered smem for BOTH operands.
//    Weight tile: [k][256] with 16B-chunk XOR swizzle c' = c ^ ((k>>2)&7):
//      - scalar staging STS hits 32 distinct banks (conflict-free),
//      - compute LDS.128 over 4 consecutive m hits 8 distinct quads (1 wf).
//    Thread computes 4 rows x 8 batches = 16 u64 f32x2 accumulators.
// ---------------------------------------------------------------------------
__global__ void __launch_bounds__(256, 2)
fc_gemm_kernel(const float* __restrict__ fcw) {
    __shared__ __align__(16) float wsh[2][FC_BK * FC_BM];  // 64 KB, swizzled
    __shared__ __align__(16) float ash[2][FC_BK][32];      //  8 KB

    const int t = threadIdx.x;
    const int mbase = blockIdx.x * FC_BM;
    const long long kbase = (long long)blockIdx.y * FC_KSEG;

    // loader mapping: thread covers rows lrow + j*32 (j=0..7), k-group lkg
    const int lrow = t >> 3;                 // 0..31
    const int lkg  = t & 7;                  // 0..7  -> k = lkg*4 + e
    const float* wsrc = fcw + (size_t)(mbase + lrow) * FC_K + kbase + lkg * 4;
    const size_t wjstride = (size_t)32 * FC_K;        // +32 rows
    const float4* asrc = (const float4*)(g_flatT + kbase * 32);

    // staging address precompute:
    // word(k, m) = k*256 + (((m>>2) ^ ((k>>2)&7)) << 2) + (m&3)
    // here m = lrow + j*32:  m>>2 = (lrow>>2) + 8j,  m&3 = lrow&3
    const int schunk = lrow >> 2;            // low 3 bits of chunk index
    const int slo    = lrow & 3;

    // compute mapping: 4 consecutive rows x 8 batches
    const int mg = t >> 2;                   // 0..63 -> rows mg*4..mg*4+3
    const int bg = t & 3;                    // 0..3  -> batches bg*8..bg*8+7

    unsigned long long acc[4][4];
#pragma unroll
    for (int r = 0; r < 4; ++r)
#pragma unroll
        for (int q = 0; q < 4; ++q) acc[r][q] = 0ull;

    float4 wreg[8];
    float4 areg;

    // ---- prologue: load + stage tile 0 ----
#pragma unroll
    for (int j = 0; j < 8; ++j)
        wreg[j] = *(const float4*)(wsrc + j * wjstride);
    areg = asrc[t];
#pragma unroll
    for (int j = 0; j < 8; ++j) {
#pragma unroll
        for (int e = 0; e < 4; ++e) {
            const int k = lkg * 4 + e;
            const int c = ((8 * j + schunk) ^ lkg) << 2;
            wsh[0][k * 256 + c + slo] = f4e(wreg[j], e);
        }
    }
    ((float4*)&ash[0][0][0])[t] = areg;
    __syncthreads();

#pragma unroll 1
    for (int c = 0; c < FC_NT; ++c) {
        const int buf = c & 1;
        const bool more = (c + 1) < FC_NT;
        if (more) {
            const float* wp = wsrc + (size_t)(c + 1) * FC_BK;
#pragma unroll
            for (int j = 0; j < 8; ++j)
                wreg[j] = *(const float4*)(wp + j * wjstride);
            areg = asrc[(size_t)(c + 1) * 256 + t];
        }

        // ---- compute 32 k on buffer `buf` ----
#pragma unroll
        for (int k = 0; k < FC_BK; ++k) {
            const float4 w4 = *(const float4*)
                &wsh[buf][k * 256 + (((mg ^ ((k >> 2) & 7)) << 2))];
            const unsigned long long wd0 = dup2(w4.x);
            const unsigned long long wd1 = dup2(w4.y);
            const unsigned long long wd2 = dup2(w4.z);
            const unsigned long long wd3 = dup2(w4.w);
            const ulonglong2 f0 = *(const ulonglong2*)&ash[buf][k][bg * 8];
            const ulonglong2 f1 = *(const ulonglong2*)&ash[buf][k][bg * 8 + 4];
            fma2(acc[0][0], wd0, f0.x); fma2(acc[0][1], wd0, f0.y);
            fma2(acc[0][2], wd0, f1.x); fma2(acc[0][3], wd0, f1.y);
            fma2(acc[1][0], wd1, f0.x); fma2(acc[1][1], wd1, f0.y);
            fma2(acc[1][2], wd1, f1.x); fma2(acc[1][3], wd1, f1.y);
            fma2(acc[2][0], wd2, f0.x); fma2(acc[2][1], wd2, f0.y);
            fma2(acc[2][2], wd2, f1.x); fma2(acc[2][3], wd2, f1.y);
            fma2(acc[3][0], wd3, f0.x); fma2(acc[3][1], wd3, f0.y);
            fma2(acc[3][2], wd3, f1.x); fma2(acc[3][3], wd3, f1.y);
        }

        if (more) {
            const int nb = buf ^ 1;
#pragma unroll
            for (int j = 0; j < 8; ++j) {
#pragma unroll
                for (int e = 0; e < 4; ++e) {
                    const int k = lkg * 4 + e;
                    const int cc = ((8 * j + schunk) ^ lkg) << 2;
                    wsh[nb][k * 256 + cc + slo] = f4e(wreg[j], e);
                }
            }
            ((float4*)&ash[nb][0][0])[t] = areg;
        }
        __syncthreads();
    }

    // ---- epilogue: rows mbase + mg*4 + r, batches bg*8..+7 ----
#pragma unroll
    for (int r = 0; r < 4; ++r) {
        float* dst = g_Cpart +
            ((size_t)blockIdx.y * FC_M + mbase + mg * 4 + r) * 32 + bg * 8;
        float2 p0 = *(float2*)&acc[r][0];
        float2 p1 = *(float2*)&acc[r][1];
        float2 p2 = *(float2*)&acc[r][2];
        float2 p3 = *(float2*)&acc[r][3];
        *(float4*)(dst)     = make_float4(p0.x, p0.y, p1.x, p1.y);
        *(float4*)(dst + 4) = make_float4(p2.x, p2.y, p3.x, p3.y);
    }
}

// ---------------------------------------------------------------------------
// 3) reduce split-K + bias + squash -> primary caps output + capsT scratch
// ---------------------------------------------------------------------------
__global__ void caps_kernel(const float* __restrict__ fcb,
                            float* __restrict__ out) {
    int idx = blockIdx.x * 256 + threadIdx.x;   // 36864
    int b = idx & 31;
    int cap = idx >> 5;
    float pc[8];
    float n2 = 0.f;
#pragma unroll
    for (int d = 0; d < 8; ++d) {
        int m = cap * 8 + d;
        float v = fcb[m];
#pragma unroll
        for (int s = 0; s < FC_SPLITK; ++s)
            v += g_Cpart[((size_t)s * FC_M + m) * 32 + b];
        pc[d] = v;
        n2 += v * v;
    }
    float scale = n2 / (1.f + n2);
    float inv = 1.f / sqrtf(n2);
#pragma unroll
    for (int d = 0; d < 8; ++d) {
        float o = scale * (pc[d] * inv + 1e-8f);
        out[OFF_PRIM + (size_t)b * 9216 + cap * 8 + d] = o;
        g_capsT[(cap * 8 + d) * 32 + b] = o;
    }
}

// ---------------------------------------------------------------------------
// 4) u_hat[b,n,p,d] = sum_i W[0,n,p,d,i] * caps[b,p,i] -> g_uhatT[n][p][d][b]
// ---------------------------------------------------------------------------
__global__ void uhat_kernel(const float* __restrict__ W) {
    int idx = blockIdx.x * 256 + threadIdx.x;   // 368640
    int b = idx & 31;
    int r = idx >> 5;                            // n*1152 + p
    int p = r % 1152;
    float caps[8];
#pragma unroll
    for (int i = 0; i < 8; ++i) caps[i] = g_capsT[(p * 8 + i) * 32 + b];
    const float* Wp = W + (size_t)r * 128;       // warp-uniform broadcast
    float* up = g_uhatT + (size_t)r * 512 + b;
#pragma unroll
    for (int d = 0; d < 16; ++d) {
        float a = 0.f;
#pragma unroll
        for (int i = 0; i < 8; ++i) a = fmaf(Wp[d * 8 + i], caps[i], a);
        up[d * 32] = a;
    }
}

// ---------------------------------------------------------------------------
// 5a) partial s sums over p-chunks of 32: spart[n][ch][d][b]
// ---------------------------------------------------------------------------
__global__ void rout_sv_kernel(int uniformC) {
    int n = blockIdx.x / 36;
    int ch = blockIdx.x - n * 36;
    int t = threadIdx.x;                         // 512 = 16 d * 32 b
    int b = t & 31;
    int d = t >> 5;
    int rbase = n * 1152 + ch * 32;
    float a = 0.f;
#pragma unroll 8
    for (int pp = 0; pp < 32; ++pp) {
        size_t r = rbase + pp;
        float c = uniformC ? 0.1f : g_cT[r * 32 + b];
        a = fmaf(c, g_uhatT[(r * 16 + d) * 32 + b], a);
    }
    g_spart[(((size_t)n * 36 + ch) * 16 + d) * 32 + b] = a;
}

// 5b) reduce partials + squash -> v (and digit caps output when final)
__global__ void rout_squash_kernel(int final_, float* __restrict__ out) {
    int t = threadIdx.x;                         // 320
    int b = t & 31;
    int n = t >> 5;
    float s[16];
    float n2 = 0.f;
#pragma unroll
    for (int d = 0; d < 16; ++d) {
        float a = 0.f;
        for (int ch = 0; ch < 36; ++ch)
            a += g_spart[(((size_t)n * 36 + ch) * 16 + d) * 32 + b];
        s[d] = a;
        n2 += a * a;
    }
    float scale = n2 / (1.f + n2);
    float inv = 1.f / sqrtf(n2);
#pragma unroll
    for (int d = 0; d < 16; ++d) {
        float v = scale * (s[d] * inv + 1e-8f);
        g_v[(n * 32 + b) * 16 + d] = v;
        if (final_) out[OFF_DIGIT + (size_t)b * 160 + n * 16 + d] = v;
    }
}

// 5c) b += sum_d u_hat * v   (first iteration: b = uv, since b starts at 0)
__global__ void rout_update_kernel(int first) {
    int idx = blockIdx.x * 256 + threadIdx.x;   // 368640
    int b = idx & 31;
    int r = idx >> 5;
    int n = r / 1152;
    const float* up = g_uhatT + (size_t)r * 512 + b;
    const float* vp = g_v + ((size_t)n * 32 + b) * 16;
    float a = 0.f;
#pragma unroll
    for (int d = 0; d < 16; ++d) a = fmaf(up[d * 32], vp[d], a);
    size_t o = (size_t)r * 32 + b;
    g_bT[o] = (first ? 0.f : g_bT[o]) + a;
}

// 5d) c = softmax over n of b; optionally emit final c and b to output
__global__ void softmax_kernel(int write_out, float* __restrict__ out) {
    int idx = blockIdx.x * 256 + threadIdx.x;   // 36864
    int b = idx & 31;
    int p = idx >> 5;
    float bv[10];
    float m = -1e30f;
#pragma unroll
    for (int n = 0; n < 10; ++n) {
        bv[n] = g_bT[((size_t)n * 1152 + p) * 32 + b];
        m = fmaxf(m, bv[n]);
    }
    float e[10];
    float sum = 0.f;
#pragma unroll
    for (int n = 0; n < 10; ++n) {
        e[n] = expf(bv[n] - m);
        sum += e[n];
    }
    float invs = 1.f / sum;
#pragma unroll
    for (int n = 0; n < 10; ++n) {
        float c = e[n] * invs;
        g_cT[((size_t)n * 1152 + p) * 32 + b] = c;
        if (write_out) {
            out[OFF_C + ((size_t)b * 10 + n) * 1152 + p] = c;
            out[OFF_B + ((size_t)b * 10 + n) * 1152 + p] = bv[n];
        }
    }
}

// ---------------------------------------------------------------------------
// 6) logits = ||digit||, argmax (first max), masked -> g_masked[i][b]
// ---------------------------------------------------------------------------
__global__ void logits_kernel(float* __restrict__ out) {
    int b = threadIdx.x;                         // 32
    float dg[160];
    for (int i = 0; i < 160; ++i) dg[i] = out[OFF_DIGIT + (size_t)b * 160 + i];
    float best = -1.f;
    int am = 0;
    for (int n = 0; n < 10; ++n) {
        float n2 = 0.f;
        for (int d = 0; d < 16; ++d) {
            float v = dg[n * 16 + d];
            n2 += v * v;
        }
        float lg = sqrtf(n2);
        out[OFF_LOGITS + b * 10 + n] = lg;
        if (lg > best) { best = lg; am = n; }
    }
    for (int n = 0; n < 10; ++n)
        for (int d = 0; d < 16; ++d)
            g_masked[(n * 16 + d) * 32 + b] = (n == am) ? dg[n * 16 + d] : 0.f;
}

// ---------------------------------------------------------------------------
// 7) decoder MLP
// ---------------------------------------------------------------------------
__global__ void dec1_kernel(const float* __restrict__ Wt,
                            const float* __restrict__ bias) {
    int idx = blockIdx.x * 256 + threadIdx.x;   // 512*32
    int b = idx & 31, o = idx >> 5;
    const float* w = Wt + (size_t)o * 160;
    float a0 = 0.f, a1 = 0.f, a2 = 0.f, a3 = 0.f;
#pragma unroll 4
    for (int i = 0; i < 160; i += 4) {
        a0 = fmaf(w[i],     g_masked[(i)     * 32 + b], a0);
        a1 = fmaf(w[i + 1], g_masked[(i + 1) * 32 + b], a1);
        a2 = fmaf(w[i + 2], g_masked[(i + 2) * 32 + b], a2);
        a3 = fmaf(w[i + 3], g_masked[(i + 3) * 32 + b], a3);
    }
    g_d1[o * 32 + b] = fmaxf(bias[o] + ((a0 + a1) + (a2 + a3)), 0.f);
}

__global__ void dec2_kernel(const float* __restrict__ Wt,
                            const float* __restrict__ bias) {
    int idx = blockIdx.x * 256 + threadIdx.x;   // 1024*32
    int b = idx & 31, o = idx >> 5;
    const float* w = Wt + (size_t)o * 512;
    float a0 = 0.f, a1 = 0.f, a2 = 0.f, a3 = 0.f;
#pragma unroll 4
    for (int i = 0; i < 512; i += 4) {
        a0 = fmaf(w[i],     g_d1[(i)     * 32 + b], a0);
        a1 = fmaf(w[i + 1], g_d1[(i + 1) * 32 + b], a1);
        a2 = fmaf(w[i + 2], g_d1[(i + 2) * 32 + b], a2);
        a3 = fmaf(w[i + 3], g_d1[(i + 3) * 32 + b], a3);
    }
    g_d2[o * 32 + b] = fmaxf(bias[o] + ((a0 + a1) + (a2 + a3)), 0.f);
}

__global__ void dec3_kernel(const float* __restrict__ Wt,
                            const float* __restrict__ bias,
                            float* __restrict__ out) {
    int idx = blockIdx.x * 256 + threadIdx.x;   // 784*32
    int b = idx & 31, o = idx >> 5;
    const float* w = Wt + (size_t)o * 1024;
    float a0 = 0.f, a1 = 0.f, a2 = 0.f, a3 = 0.f;
#pragma unroll 4
    for (int i = 0; i < 1024; i += 4) {
        a0 = fmaf(w[i],     g_d2[(i)     * 32 + b], a0);
        a1 = fmaf(w[i + 1], g_d2[(i + 1) * 32 + b], a1);
        a2 = fmaf(w[i + 2], g_d2[(i + 2) * 32 + b], a2);
        a3 = fmaf(w[i + 3], g_d2[(i + 3) * 32 + b], a3);
    }
    float x = bias[o] + ((a0 + a1) + (a2 + a3));
    out[OFF_RECON + (size_t)b * 784 + o] = 1.f / (1.f + expf(-x));
}

// ---------------------------------------------------------------------------
// Resolve inputs by (unique) element count — order-independent binding.
// ---------------------------------------------------------------------------
static const float* by_size(void* const* d_in, const int* s, int n, int want) {
    for (int i = 0; i < n; ++i)
        if (s[i] == want) return (const float*)d_in[i];
    return nullptr;
}

extern "C" void kernel_launch(void* const* d_in, const int* in_sizes, int n_in,
                              void* d_out, int out_size) {
    const float* x   = by_size(d_in, in_sizes, n_in, 32 * 784);        // 25088
    const float* cw  = by_size(d_in, in_sizes, n_in, 256 * 81);        // 20736
    const float* cb  = by_size(d_in, in_sizes, n_in, 256);
    const float* fcw = by_size(d_in, in_sizes, n_in, 943718400);       // 9216*102400
    const float* fcb = by_size(d_in, in_sizes, n_in, 9216);
    const float* W   = by_size(d_in, in_sizes, n_in, 1474560);         // 10*1152*16*8
    const float* d1w = by_size(d_in, in_sizes, n_in, 512 * 160);       // 81920
    const float* d1b = by_size(d_in, in_sizes, n_in, 512);
    const float* d2w = by_size(d_in, in_sizes, n_in, 1024 * 512);      // 524288
    const float* d2b = by_size(d_in, in_sizes, n_in, 1024);
    const float* d3w = by_size(d_in, in_sizes, n_in, 784 * 1024);      // 802816
    const float* d3b = by_size(d_in, in_sizes, n_in, 784);
    float* out = (float*)d_out;

    xT_kernel<<<98, 256>>>(x);                           // launch 1
    conv_kernel<<<12800, 256>>>(cw, cb);                 // launch 2
    prep_kernel<<<1, 256>>>();                           // launch 3
    fc_gemm_kernel<<<dim3(36, 16), 256>>>(fcw);          // launch 4 <- ncu slot
    caps_kernel<<<144, 256>>>(fcb, out);
    uhat_kernel<<<1440, 256>>>(W);

    // routing iteration 0 (c = softmax(0) = 0.1 uniform)
    rout_sv_kernel<<<360, 512>>>(1);
    rout_squash_kernel<<<1, 320>>>(0, out);
    rout_update_kernel<<<1440, 256>>>(1);
    // routing iteration 1
    softmax_kernel<<<144, 256>>>(0, out);
    rout_sv_kernel<<<360, 512>>>(0);
    rout_squash_kernel<<<1, 320>>>(0, out);
    rout_update_kernel<<<1440, 256>>>(0);
    // final pass (emit c, b, digit caps)
    softmax_kernel<<<144, 256>>>(1, out);
    rout_sv_kernel<<<360, 512>>>(0);
    rout_squash_kernel<<<1, 320>>>(1, out);

    logits_kernel<<<1, 32>>>(out);
    dec1_kernel<<<64, 256>>>(d1w, d1b);
    dec2_kernel<<<128, 256>>>(d2w, d2b);
    dec3_kernel<<<98, 256>>>(d3w, d3b, out);
}